// round 2
// baseline (speedup 1.0000x reference)
#include <cuda_runtime.h>

#define NB 256
#define NS 1024
#define ND 512

__device__ __forceinline__ float fast_tanh(float x) {
    // tanh(x) = 1 - 2/(1 + exp(2x));  exp(2x) = ex2(x * 2*log2(e))
    float u;
    asm("ex2.approx.f32 %0, %1;" : "=f"(u) : "f"(x * 2.8853900817779268f));
    float r;
    asm("rcp.approx.f32 %0, %1;" : "=f"(r) : "f"(u + 1.0f));
    return fmaf(-2.0f, r, 1.0f);
}

__device__ __forceinline__ float fast_exp2(float x) {
    float y;
    asm("ex2.approx.f32 %0, %1;" : "=f"(y) : "f"(x));
    return y;
}

__global__ __launch_bounds__(256, 2)
void memn2n_kernel(const float* __restrict__ story,
                   const float* __restrict__ query,
                   const float* __restrict__ Wa_w,
                   float* __restrict__ out)
{
    const int b    = blockIdx.x;
    const int tid  = threadIdx.x;
    const int warp = tid >> 5;
    const int lane = tid & 31;

    __shared__ float sm_m[8];
    __shared__ float sm_l[8];
    __shared__ float sm_acc[ND];

    // zero the merge buffer (ordered by the __syncthreads below)
    for (int i = tid; i < ND; i += 256) sm_acc[i] = 0.0f;

    // lane owns d = 128*k + 4*lane + j  (k=0..3, j=0..3) -> 4 coalesced float4
    const float* qb = query + b * ND;
    float4 q[4], w[4];
#pragma unroll
    for (int k = 0; k < 4; k++) {
        q[k] = *(const float4*)(qb   + k * 128 + 4 * lane);
        w[k] = *(const float4*)(Wa_w + k * 128 + 4 * lane);
    }

    const float* sb = story + (size_t)b * NS * ND;

    float m = -1e30f;
    float l = 0.0f;
    float4 acc[4];
#pragma unroll
    for (int k = 0; k < 4; k++) acc[k] = make_float4(0.f, 0.f, 0.f, 0.f);

    const float LOG2E = 1.4426950408889634f;

    // prefetch first row for this warp
    float4 x[4], xn[4];
    {
        const float* p = sb + (size_t)warp * ND;
#pragma unroll
        for (int k = 0; k < 4; k++)
            xn[k] = __ldcs((const float4*)(p + k * 128 + 4 * lane));
    }

    for (int s = warp; s < NS; s += 8) {
#pragma unroll
        for (int k = 0; k < 4; k++) x[k] = xn[k];

        const int sn = s + 8;
        if (sn < NS) {
            const float* p = sb + (size_t)sn * ND;
#pragma unroll
            for (int k = 0; k < 4; k++)
                xn[k] = __ldcs((const float4*)(p + k * 128 + 4 * lane));
        }

        // partial dot: sum_d tanh(x + q) * w   (bias dropped: softmax-invariant)
        float part = 0.0f;
#pragma unroll
        for (int k = 0; k < 4; k++) {
            part = fmaf(fast_tanh(x[k].x + q[k].x), w[k].x, part);
            part = fmaf(fast_tanh(x[k].y + q[k].y), w[k].y, part);
            part = fmaf(fast_tanh(x[k].z + q[k].z), w[k].z, part);
            part = fmaf(fast_tanh(x[k].w + q[k].w), w[k].w, part);
        }
#pragma unroll
        for (int off = 16; off > 0; off >>= 1)
            part += __shfl_xor_sync(0xffffffffu, part, off);

        // online softmax update in base 2
        const float t     = part * LOG2E;
        const float mn    = fmaxf(m, t);
        const float alpha = fast_exp2(m - mn);
        const float p     = fast_exp2(t - mn);
        l = fmaf(l, alpha, p);
        m = mn;

#pragma unroll
        for (int k = 0; k < 4; k++) {
            acc[k].x = fmaf(acc[k].x, alpha, p * x[k].x);
            acc[k].y = fmaf(acc[k].y, alpha, p * x[k].y);
            acc[k].z = fmaf(acc[k].z, alpha, p * x[k].z);
            acc[k].w = fmaf(acc[k].w, alpha, p * x[k].w);
        }
    }

    // cross-warp merge
    if (lane == 0) { sm_m[warp] = m; sm_l[warp] = l; }
    __syncthreads();

    float M = sm_m[0];
#pragma unroll
    for (int i = 1; i < 8; i++) M = fmaxf(M, sm_m[i]);
    float L = 0.0f;
#pragma unroll
    for (int i = 0; i < 8; i++) L += sm_l[i] * fast_exp2(sm_m[i] - M);

    const float f = fast_exp2(m - M);
#pragma unroll
    for (int k = 0; k < 4; k++) {
        const int d0 = k * 128 + 4 * lane;
        atomicAdd(&sm_acc[d0 + 0], acc[k].x * f);
        atomicAdd(&sm_acc[d0 + 1], acc[k].y * f);
        atomicAdd(&sm_acc[d0 + 2], acc[k].z * f);
        atomicAdd(&sm_acc[d0 + 3], acc[k].w * f);
    }
    __syncthreads();

    const float inv = 1.0f / L;
    float* ob = out + b * ND;
    for (int i = tid; i < ND; i += 256)
        ob[i] = sm_acc[i] * inv;
}

extern "C" void kernel_launch(void* const* d_in, const int* in_sizes, int n_in,
                              void* d_out, int out_size)
{
    const float* story = (const float*)d_in[0];
    const float* query = (const float*)d_in[1];
    const float* Wa_w  = (const float*)d_in[2];
    // d_in[3] = Wa_b: cancels inside softmax, unused.
    (void)in_sizes; (void)n_in; (void)out_size;

    memn2n_kernel<<<NB, 256>>>(story, query, Wa_w, (float*)d_out);
}